// round 1
// baseline (speedup 1.0000x reference)
#include <cuda_runtime.h>

// Problem constants
#define Bb   8
#define Mm   512
#define Ll   1024
#define Hh   512
#define Kk   8
#define Dd   64
#define SKk  1536           // M + L
#define BKC  64             // B * K
#define SCALE 0.125f        // 1/sqrt(64)

// Scratch (device globals — no dynamic allocation allowed)
__device__ float g_q[BKC * (size_t)Mm * Dd];      //  8 MB
__device__ float g_k[BKC * (size_t)SKk * Dd];     // 24 MB
__device__ float g_v[BKC * (size_t)SKk * Dd];     // 24 MB
__device__ float g_ctx[(size_t)Bb * Mm * Hh];     //  8 MB  [B, M, K, D]

// ---------------------------------------------------------------------------
// Projection GEMM: Y = X @ W^T with head-split store.
// X: [rows, 512] (rows = B*S), W: [512, 512] (out-major).
// Y[(b*K + kh)*S + s][d]  where output feature c = kh*64 + d.
// Tile 64x64, BK=16, 256 threads, 4x4 micro-tile.
// ---------------------------------------------------------------------------
__global__ void proj_head_kernel(const float* __restrict__ X,
                                 const float* __restrict__ W,
                                 int S, int sel) {
    __shared__ float As[16][68];
    __shared__ float Bs[16][68];
    float* __restrict__ Y = (sel == 0) ? g_q : (sel == 1 ? g_k : g_v);

    const int tid  = threadIdx.x;
    const int row0 = blockIdx.x * 64;
    const int col0 = blockIdx.y * 64;
    const int tr = tid >> 4;           // 0..15
    const int tc = tid & 15;           // 0..15
    const int lr = tid >> 2;           // 0..63
    const int lc = (tid & 3) << 2;     // 0,4,8,12

    float acc[4][4];
#pragma unroll
    for (int i = 0; i < 4; i++)
#pragma unroll
        for (int j = 0; j < 4; j++) acc[i][j] = 0.f;

    for (int k0 = 0; k0 < 512; k0 += 16) {
        float4 xa = *(const float4*)(X + (size_t)(row0 + lr) * 512 + k0 + lc);
        As[lc + 0][lr] = xa.x; As[lc + 1][lr] = xa.y;
        As[lc + 2][lr] = xa.z; As[lc + 3][lr] = xa.w;
        float4 wb = *(const float4*)(W + (size_t)(col0 + lr) * 512 + k0 + lc);
        Bs[lc + 0][lr] = wb.x; Bs[lc + 1][lr] = wb.y;
        Bs[lc + 2][lr] = wb.z; Bs[lc + 3][lr] = wb.w;
        __syncthreads();
#pragma unroll
        for (int kk = 0; kk < 16; kk++) {
            float4 a4 = *(const float4*)&As[kk][tr << 2];
            float4 b4 = *(const float4*)&Bs[kk][tc << 2];
            float a[4] = {a4.x, a4.y, a4.z, a4.w};
            float b[4] = {b4.x, b4.y, b4.z, b4.w};
#pragma unroll
            for (int i = 0; i < 4; i++)
#pragma unroll
                for (int j = 0; j < 4; j++) acc[i][j] += a[i] * b[j];
        }
        __syncthreads();
    }

#pragma unroll
    for (int i = 0; i < 4; i++) {
        int r = row0 + (tr << 2) + i;
        int b = r / S, s = r - b * S;
#pragma unroll
        for (int j = 0; j < 4; j++) {
            int c  = col0 + (tc << 2) + j;
            int kh = c >> 6, d = c & 63;
            Y[((size_t)(b * Kk + kh) * S + s) * Dd + d] = acc[i][j];
        }
    }
}

// ---------------------------------------------------------------------------
// Output GEMM: out = g_ctx([4096,512]) @ Wo^T, plain store.
// ---------------------------------------------------------------------------
__global__ void proj_out_kernel(const float* __restrict__ W,
                                float* __restrict__ O) {
    __shared__ float As[16][68];
    __shared__ float Bs[16][68];
    const int tid  = threadIdx.x;
    const int row0 = blockIdx.x * 64;
    const int col0 = blockIdx.y * 64;
    const int tr = tid >> 4, tc = tid & 15;
    const int lr = tid >> 2, lc = (tid & 3) << 2;

    float acc[4][4];
#pragma unroll
    for (int i = 0; i < 4; i++)
#pragma unroll
        for (int j = 0; j < 4; j++) acc[i][j] = 0.f;

    for (int k0 = 0; k0 < 512; k0 += 16) {
        float4 xa = *(const float4*)(g_ctx + (size_t)(row0 + lr) * 512 + k0 + lc);
        As[lc + 0][lr] = xa.x; As[lc + 1][lr] = xa.y;
        As[lc + 2][lr] = xa.z; As[lc + 3][lr] = xa.w;
        float4 wb = *(const float4*)(W + (size_t)(col0 + lr) * 512 + k0 + lc);
        Bs[lc + 0][lr] = wb.x; Bs[lc + 1][lr] = wb.y;
        Bs[lc + 2][lr] = wb.z; Bs[lc + 3][lr] = wb.w;
        __syncthreads();
#pragma unroll
        for (int kk = 0; kk < 16; kk++) {
            float4 a4 = *(const float4*)&As[kk][tr << 2];
            float4 b4 = *(const float4*)&Bs[kk][tc << 2];
            float a[4] = {a4.x, a4.y, a4.z, a4.w};
            float b[4] = {b4.x, b4.y, b4.z, b4.w};
#pragma unroll
            for (int i = 0; i < 4; i++)
#pragma unroll
                for (int j = 0; j < 4; j++) acc[i][j] += a[i] * b[j];
        }
        __syncthreads();
    }

#pragma unroll
    for (int i = 0; i < 4; i++) {
        int r = row0 + (tr << 2) + i;
#pragma unroll
        for (int j = 0; j < 4; j++) {
            int c = col0 + (tc << 2) + j;
            O[(size_t)r * 512 + c] = acc[i][j];
        }
    }
}

// ---------------------------------------------------------------------------
// Fused banded attention with online softmax + post-softmax span mask.
// CTA = (32 query rows, one bk head). Chunks of 64 keys, 16 chunks.
//   score[i, j] = (q_i . k_{i+j} + q_i . pe[:, j]) * SCALE
//   p = softmax_j(score);  p_masked = p * mask(head, j)   (l excludes mask!)
//   out[i, d] = sum_j p_masked * v[i+j, d]
// Thread map: row = tid/8, tg = tid%8.
//   score phase: thread owns t = tg + 8*i (i<8)
//   AV phase   : thread owns d = tg*8 .. tg*8+7
// ---------------------------------------------------------------------------
#define MT  32
#define JT  64
#define QSS 68
#define KTS 97
#define VSS 68
#define PES 64
#define PSS 68
#define ATTN_SMEM_FLOATS (MT * QSS + 64 * KTS + 96 * VSS + 64 * PES + MT * PSS)

__global__ void attn_kernel(const float* __restrict__ pe,
                            const float* __restrict__ span_val) {
    extern __shared__ float sm[];
    float* Qs  = sm;                   // [MT][QSS]
    float* Kct = Qs + MT * QSS;        // [64][KTS]  transposed K slab
    float* Vc  = Kct + 64 * KTS;       // [96][VSS]
    float* PEc = Vc + 96 * VSS;        // [64][PES]
    float* Ps  = PEc + 64 * PES;       // [MT][PSS]

    const int tid = threadIdx.x;
    const int bk  = blockIdx.y;
    const int i0  = blockIdx.x * MT;
    const int kh  = bk & 7;
    const int row = tid >> 3;
    const int tg  = tid & 7;
    const float spanL = span_val[kh] * 1024.f;

    // Q tile
    {
        const float* qbase = g_q + ((size_t)bk * Mm + i0) * Dd;
#pragma unroll
        for (int it = 0; it < 2; it++) {
            int f = tid + it * 256;            // float4 id 0..511
            int r = f >> 4, c4 = (f & 15) << 2;
            float4 v = *(const float4*)(qbase + (size_t)r * Dd + c4);
            *(float4*)&Qs[r * QSS + c4] = v;
        }
    }

    float m_run = -1e30f, l_run = 0.f;
    float acc[8];
#pragma unroll
    for (int i = 0; i < 8; i++) acc[i] = 0.f;

    for (int jc = 0; jc < Ll; jc += JT) {
        __syncthreads();   // protect slab overwrite vs previous AV
        // K (transposed), V, PE slabs. Slab rows u=0..95 map to key i0+jc+u.
        const float* kbase = g_k + ((size_t)bk * SKk + i0 + jc) * Dd;
        const float* vbase = g_v + ((size_t)bk * SKk + i0 + jc) * Dd;
#pragma unroll
        for (int it = 0; it < 6; it++) {
            int u = (tid >> 4) + it * 16;      // 0..95
            int c = (tid & 15) << 2;
            float4 kv = *(const float4*)(kbase + (size_t)u * Dd + c);
            Kct[(c + 0) * KTS + u] = kv.x;
            Kct[(c + 1) * KTS + u] = kv.y;
            Kct[(c + 2) * KTS + u] = kv.z;
            Kct[(c + 3) * KTS + u] = kv.w;
            float4 vv = *(const float4*)(vbase + (size_t)u * Dd + c);
            *(float4*)&Vc[u * VSS + c] = vv;
        }
#pragma unroll
        for (int it = 0; it < 4; it++) {
            int f = tid + it * 256;            // float4 id 0..1023
            int d = f >> 4, c4 = (f & 15) << 2;
            float4 v = *(const float4*)(pe + (size_t)d * Ll + jc + c4);
            *(float4*)&PEc[d * PES + c4] = v;
        }
        __syncthreads();

        // scores for t = tg + 8*i
        float s[8];
#pragma unroll
        for (int i = 0; i < 8; i++) s[i] = 0.f;
#pragma unroll 4
        for (int d = 0; d < 64; d++) {
            float qv = Qs[row * QSS + d];
            const float* krow  = &Kct[d * KTS + row + tg];
            const float* perow = &PEc[d * PES + tg];
#pragma unroll
            for (int i = 0; i < 8; i++) {
                s[i] += qv * krow[8 * i];
                s[i] += qv * perow[8 * i];
            }
        }

        // online softmax (8 threads per row, contiguous lanes)
        float mloc = -1e30f;
#pragma unroll
        for (int i = 0; i < 8; i++) { s[i] *= SCALE; mloc = fmaxf(mloc, s[i]); }
#pragma unroll
        for (int off = 1; off < 8; off <<= 1)
            mloc = fmaxf(mloc, __shfl_xor_sync(0xFFFFFFFFu, mloc, off));
        float m_new = fmaxf(m_run, mloc);
        float corr  = __expf(m_run - m_new);
        l_run *= corr;
#pragma unroll
        for (int i = 0; i < 8; i++) acc[i] *= corr;

        float p[8], psum = 0.f;
#pragma unroll
        for (int i = 0; i < 8; i++) { p[i] = __expf(s[i] - m_new); psum += p[i]; }
#pragma unroll
        for (int off = 1; off < 8; off <<= 1)
            psum += __shfl_xor_sync(0xFFFFFFFFu, psum, off);
        l_run += psum;          // normalizer uses UNmasked exp (matches ref)
        m_run = m_new;

        // masked probabilities to smem
#pragma unroll
        for (int i = 0; i < 8; i++) {
            int t = tg + 8 * i;
            float jj = (float)(jc + t);
            float mk = fminf(1.f, fmaxf(0.f, (jj - 1023.f + spanL) * (1.f / 32.f) + 1.f));
            Ps[row * PSS + t] = p[i] * mk;
        }
        __syncthreads();

        // AV: acc[d] += p[t] * V[row + t][d], d = tg*8..tg*8+7
        const float* vr = &Vc[row * VSS + tg * 8];
#pragma unroll 8
        for (int t = 0; t < JT; t++) {
            float pv = Ps[row * PSS + t];
            float4 v0 = *(const float4*)(vr + t * VSS);
            float4 v1 = *(const float4*)(vr + t * VSS + 4);
            acc[0] += pv * v0.x; acc[1] += pv * v0.y;
            acc[2] += pv * v0.z; acc[3] += pv * v0.w;
            acc[4] += pv * v1.x; acc[5] += pv * v1.y;
            acc[6] += pv * v1.z; acc[7] += pv * v1.w;
        }
    }

    // normalize + store ctx[b][m][kh][d]
    float invl = 1.f / l_run;
    int b = bk >> 3;
    float* obase = g_ctx + ((size_t)(b * Mm + i0 + row) * Kk + kh) * Dd + tg * 8;
    float4 o0 = make_float4(acc[0] * invl, acc[1] * invl, acc[2] * invl, acc[3] * invl);
    float4 o1 = make_float4(acc[4] * invl, acc[5] * invl, acc[6] * invl, acc[7] * invl);
    *(float4*)obase       = o0;
    *(float4*)(obase + 4) = o1;
}

// ---------------------------------------------------------------------------
extern "C" void kernel_launch(void* const* d_in, const int* in_sizes, int n_in,
                              void* d_out, int out_size) {
    const float* query = (const float*)d_in[0];
    const float* key   = (const float*)d_in[1];
    const float* value = (const float*)d_in[2];
    const float* pe    = (const float*)d_in[3];
    const float* Wq    = (const float*)d_in[4];
    const float* Wk    = (const float*)d_in[5];
    const float* Wv    = (const float*)d_in[6];
    const float* Wo    = (const float*)d_in[7];
    const float* span  = (const float*)d_in[8];
    float* out = (float*)d_out;

    cudaFuncSetAttribute(attn_kernel,
                         cudaFuncAttributeMaxDynamicSharedMemorySize,
                         ATTN_SMEM_FLOATS * (int)sizeof(float));

    // Projections into head-split scratch
    proj_head_kernel<<<dim3(Bb * Mm / 64, Hh / 64), 256>>>(query, Wq, Mm, 0);
    proj_head_kernel<<<dim3(Bb * SKk / 64, Hh / 64), 256>>>(key, Wk, SKk, 1);
    proj_head_kernel<<<dim3(Bb * SKk / 64, Hh / 64), 256>>>(value, Wv, SKk, 2);

    // Fused banded attention
    attn_kernel<<<dim3(Mm / MT, BKC), 256,
                  ATTN_SMEM_FLOATS * (int)sizeof(float)>>>(pe, span);

    // Output projection
    proj_out_kernel<<<dim3(Bb * Mm / 64, Hh / 64), 256>>>(Wo, out);
}

// round 2
// speedup vs baseline: 1.1624x; 1.1624x over previous
#include <cuda_runtime.h>
#include <cstdint>

// Problem constants
#define Bb   8
#define Mm   512
#define Ll   1024
#define Hh   512
#define Kk   8
#define Dd   64
#define SKk  1536           // M + L
#define BKC  64             // B * K
#define SCALE 0.125f        // 1/sqrt(64)

// Scratch (device globals — no dynamic allocation allowed)
__device__ float g_q[BKC * (size_t)Mm * Dd];      //  8 MB
__device__ float g_k[BKC * (size_t)SKk * Dd];     // 24 MB
__device__ float g_v[BKC * (size_t)SKk * Dd];     // 24 MB
__device__ float g_ctx[(size_t)Bb * Mm * Hh];     //  8 MB  [B, M, K, D]

// ---------------------------------------------------------------------------
// Split-tf32 tensor-core projection GEMM:  Y = X @ W^T
//   X: [rows, 512] fp32, W: [512, 512] fp32 (out-feature-major).
//   Each fp32 operand is split hi/lo (hi = top-11-bit mantissa, lo = exact
//   residual); 3 MMA passes (hi*hi + hi*lo + lo*hi) give ~fp32 accuracy.
// CTA: 256 thr, tile 128x128, warp tile 32x64, k-chunk 32.
// sel: 0->g_q 1->g_k 2->g_v (head-split store), 3-> plain store to Yout
//      (X is taken from g_ctx when sel==3).
// ---------------------------------------------------------------------------
#define PSTR 36   // smem row stride (32 + 4 pad floats)

#define MMA_TF32(c, a0, a1, a2, a3, b0, b1)                                   \
    asm volatile(                                                             \
        "mma.sync.aligned.m16n8k8.row.col.f32.tf32.tf32.f32 "                 \
        "{%0,%1,%2,%3},{%4,%5,%6,%7},{%8,%9},{%0,%1,%2,%3};"                  \
        : "+f"(c[0]), "+f"(c[1]), "+f"(c[2]), "+f"(c[3])                      \
        : "r"(a0), "r"(a1), "r"(a2), "r"(a3), "r"(b0), "r"(b1));

__global__ __launch_bounds__(256) void proj_mma_kernel(
        const float* __restrict__ Xin, const float* __restrict__ W,
        float* __restrict__ Yout, int S, int sel) {
    __shared__ float Xs[128 * PSTR];
    __shared__ float Ws[128 * PSTR];

    const float* __restrict__ X = (sel == 3) ? g_ctx : Xin;

    const int tid  = threadIdx.x;
    const int lane = tid & 31;
    const int wid  = tid >> 5;
    const int warp_m = wid >> 1;       // 0..3
    const int warp_n = wid & 1;        // 0..1
    const int gid = lane >> 2;         // 0..7
    const int tig = lane & 3;          // 0..3
    const int row0 = blockIdx.x * 128;
    const int col0 = blockIdx.y * 128;

    float c[2][8][4];
#pragma unroll
    for (int f = 0; f < 2; f++)
#pragma unroll
        for (int j = 0; j < 8; j++)
#pragma unroll
            for (int t = 0; t < 4; t++) c[f][j][t] = 0.f;

    for (int k0 = 0; k0 < 512; k0 += 32) {
        // stage X[128x32] and W[128x32]
#pragma unroll
        for (int i = 0; i < 4; i++) {
            int f4 = tid + i * 256;
            int r  = f4 >> 3;
            int kq = (f4 & 7) << 2;
            float4 xv = *(const float4*)(X + (size_t)(row0 + r) * 512 + k0 + kq);
            *(float4*)&Xs[r * PSTR + kq] = xv;
            float4 wv = *(const float4*)(W + (size_t)(col0 + r) * 512 + k0 + kq);
            *(float4*)&Ws[r * PSTR + kq] = wv;
        }
        __syncthreads();

#pragma unroll
        for (int kk = 0; kk < 32; kk += 8) {
            // A fragments (rows warp_m*32 .. +31), hi/lo split
            uint32_t ahi[2][4], alo[2][4];
#pragma unroll
            for (int f = 0; f < 2; f++) {
                int rbase = warp_m * 32 + f * 16 + gid;
#pragma unroll
                for (int rg = 0; rg < 4; rg++) {
                    int r    = rbase + ((rg & 1) << 3);
                    int kcol = kk + tig + ((rg >> 1) << 2);
                    float x  = Xs[r * PSTR + kcol];
                    uint32_t hb = __float_as_uint(x) & 0xFFFFE000u;
                    ahi[f][rg] = hb;
                    alo[f][rg] = __float_as_uint(x - __uint_as_float(hb));
                }
            }
#pragma unroll
            for (int j = 0; j < 8; j++) {
                int cidx = warp_n * 64 + j * 8 + gid;
                float b0f = Ws[cidx * PSTR + kk + tig];
                float b1f = Ws[cidx * PSTR + kk + tig + 4];
                uint32_t b0h = __float_as_uint(b0f) & 0xFFFFE000u;
                uint32_t b1h = __float_as_uint(b1f) & 0xFFFFE000u;
                uint32_t b0l = __float_as_uint(b0f - __uint_as_float(b0h));
                uint32_t b1l = __float_as_uint(b1f - __uint_as_float(b1h));
#pragma unroll
                for (int f = 0; f < 2; f++) {
                    MMA_TF32(c[f][j], ahi[f][0], ahi[f][1], ahi[f][2], ahi[f][3], b0h, b1h);
                    MMA_TF32(c[f][j], ahi[f][0], ahi[f][1], ahi[f][2], ahi[f][3], b0l, b1l);
                    MMA_TF32(c[f][j], alo[f][0], alo[f][1], alo[f][2], alo[f][3], b0h, b1h);
                }
            }
        }
        __syncthreads();
    }

    // epilogue: float2 stores (cols 2*tig, 2*tig+1 are adjacent)
    float* __restrict__ Yh = (sel == 0) ? g_q : (sel == 1 ? g_k : g_v);
#pragma unroll
    for (int f = 0; f < 2; f++) {
        int rloc = warp_m * 32 + f * 16 + gid;
#pragma unroll
        for (int j = 0; j < 8; j++) {
            int cc = col0 + warp_n * 64 + j * 8 + 2 * tig;
#pragma unroll
            for (int h = 0; h < 2; h++) {          // h: row offset 0 / +8
                int r = row0 + rloc + h * 8;
                float2 val = make_float2(c[f][j][h * 2], c[f][j][h * 2 + 1]);
                if (sel == 3) {
                    *(float2*)(Yout + (size_t)r * 512 + cc) = val;
                } else {
                    int b = r / S, s = r - b * S;
                    int kh = cc >> 6, d = cc & 63;
                    *(float2*)(Yh + ((size_t)(b * Kk + kh) * S + s) * Dd + d) = val;
                }
            }
        }
    }
}

// ---------------------------------------------------------------------------
// Fused banded attention with online softmax + post-softmax span mask.
// (unchanged from round 1 — L1-bound; to be MMA-ized next round)
// ---------------------------------------------------------------------------
#define MT  32
#define JT  64
#define QSS 68
#define KTS 97
#define VSS 68
#define PES 64
#define PSS 68
#define ATTN_SMEM_FLOATS (MT * QSS + 64 * KTS + 96 * VSS + 64 * PES + MT * PSS)

__global__ void attn_kernel(const float* __restrict__ pe,
                            const float* __restrict__ span_val) {
    extern __shared__ float sm[];
    float* Qs  = sm;                   // [MT][QSS]
    float* Kct = Qs + MT * QSS;        // [64][KTS]  transposed K slab
    float* Vc  = Kct + 64 * KTS;       // [96][VSS]
    float* PEc = Vc + 96 * VSS;        // [64][PES]
    float* Ps  = PEc + 64 * PES;       // [MT][PSS]

    const int tid = threadIdx.x;
    const int bk  = blockIdx.y;
    const int i0  = blockIdx.x * MT;
    const int kh  = bk & 7;
    const int row = tid >> 3;
    const int tg  = tid & 7;
    const float spanL = span_val[kh] * 1024.f;

    // Q tile
    {
        const float* qbase = g_q + ((size_t)bk * Mm + i0) * Dd;
#pragma unroll
        for (int it = 0; it < 2; it++) {
            int f = tid + it * 256;            // float4 id 0..511
            int r = f >> 4, c4 = (f & 15) << 2;
            float4 v = *(const float4*)(qbase + (size_t)r * Dd + c4);
            *(float4*)&Qs[r * QSS + c4] = v;
        }
    }

    float m_run = -1e30f, l_run = 0.f;
    float acc[8];
#pragma unroll
    for (int i = 0; i < 8; i++) acc[i] = 0.f;

    for (int jc = 0; jc < Ll; jc += JT) {
        __syncthreads();   // protect slab overwrite vs previous AV
        const float* kbase = g_k + ((size_t)bk * SKk + i0 + jc) * Dd;
        const float* vbase = g_v + ((size_t)bk * SKk + i0 + jc) * Dd;
#pragma unroll
        for (int it = 0; it < 6; it++) {
            int u = (tid >> 4) + it * 16;      // 0..95
            int c = (tid & 15) << 2;
            float4 kv = *(const float4*)(kbase + (size_t)u * Dd + c);
            Kct[(c + 0) * KTS + u] = kv.x;
            Kct[(c + 1) * KTS + u] = kv.y;
            Kct[(c + 2) * KTS + u] = kv.z;
            Kct[(c + 3) * KTS + u] = kv.w;
            float4 vv = *(const float4*)(vbase + (size_t)u * Dd + c);
            *(float4*)&Vc[u * VSS + c] = vv;
        }
#pragma unroll
        for (int it = 0; it < 4; it++) {
            int f = tid + it * 256;            // float4 id 0..1023
            int d = f >> 4, c4 = (f & 15) << 2;
            float4 v = *(const float4*)(pe + (size_t)d * Ll + jc + c4);
            *(float4*)&PEc[d * PES + c4] = v;
        }
        __syncthreads();

        // scores for t = tg + 8*i
        float s[8];
#pragma unroll
        for (int i = 0; i < 8; i++) s[i] = 0.f;
#pragma unroll 4
        for (int d = 0; d < 64; d++) {
            float qv = Qs[row * QSS + d];
            const float* krow  = &Kct[d * KTS + row + tg];
            const float* perow = &PEc[d * PES + tg];
#pragma unroll
            for (int i = 0; i < 8; i++) {
                s[i] += qv * krow[8 * i];
                s[i] += qv * perow[8 * i];
            }
        }

        // online softmax (8 threads per row, contiguous lanes)
        float mloc = -1e30f;
#pragma unroll
        for (int i = 0; i < 8; i++) { s[i] *= SCALE; mloc = fmaxf(mloc, s[i]); }
#pragma unroll
        for (int off = 1; off < 8; off <<= 1)
            mloc = fmaxf(mloc, __shfl_xor_sync(0xFFFFFFFFu, mloc, off));
        float m_new = fmaxf(m_run, mloc);
        float corr  = __expf(m_run - m_new);
        l_run *= corr;
#pragma unroll
        for (int i = 0; i < 8; i++) acc[i] *= corr;

        float p[8], psum = 0.f;
#pragma unroll
        for (int i = 0; i < 8; i++) { p[i] = __expf(s[i] - m_new); psum += p[i]; }
#pragma unroll
        for (int off = 1; off < 8; off <<= 1)
            psum += __shfl_xor_sync(0xFFFFFFFFu, psum, off);
        l_run += psum;          // normalizer uses UNmasked exp (matches ref)
        m_run = m_new;

        // masked probabilities to smem
#pragma unroll
        for (int i = 0; i < 8; i++) {
            int t = tg + 8 * i;
            float jj = (float)(jc + t);
            float mk = fminf(1.f, fmaxf(0.f, (jj - 1023.f + spanL) * (1.f / 32.f) + 1.f));
            Ps[row * PSS + t] = p[i] * mk;
        }
        __syncthreads();

        // AV: acc[d] += p[t] * V[row + t][d], d = tg*8..tg*8+7
        const float* vr = &Vc[row * VSS + tg * 8];
#pragma unroll 8
        for (int t = 0; t < JT; t++) {
            float pv = Ps[row * PSS + t];
            float4 v0 = *(const float4*)(vr + t * VSS);
            float4 v1 = *(const float4*)(vr + t * VSS + 4);
            acc[0] += pv * v0.x; acc[1] += pv * v0.y;
            acc[2] += pv * v0.z; acc[3] += pv * v0.w;
            acc[4] += pv * v1.x; acc[5] += pv * v1.y;
            acc[6] += pv * v1.z; acc[7] += pv * v1.w;
        }
    }

    // normalize + store ctx[b][m][kh][d]
    float invl = 1.f / l_run;
    int b = bk >> 3;
    float* obase = g_ctx + ((size_t)(b * Mm + i0 + row) * Kk + kh) * Dd + tg * 8;
    float4 o0 = make_float4(acc[0] * invl, acc[1] * invl, acc[2] * invl, acc[3] * invl);
    float4 o1 = make_float4(acc[4] * invl, acc[5] * invl, acc[6] * invl, acc[7] * invl);
    *(float4*)obase       = o0;
    *(float4*)(obase + 4) = o1;
}

// ---------------------------------------------------------------------------
extern "C" void kernel_launch(void* const* d_in, const int* in_sizes, int n_in,
                              void* d_out, int out_size) {
    const float* query = (const float*)d_in[0];
    const float* key   = (const float*)d_in[1];
    const float* value = (const float*)d_in[2];
    const float* pe    = (const float*)d_in[3];
    const float* Wq    = (const float*)d_in[4];
    const float* Wk    = (const float*)d_in[5];
    const float* Wv    = (const float*)d_in[6];
    const float* Wo    = (const float*)d_in[7];
    const float* span  = (const float*)d_in[8];
    float* out = (float*)d_out;

    cudaFuncSetAttribute(attn_kernel,
                         cudaFuncAttributeMaxDynamicSharedMemorySize,
                         ATTN_SMEM_FLOATS * (int)sizeof(float));

    // Projections into head-split scratch (split-tf32 tensor cores)
    proj_mma_kernel<<<dim3(Bb * Mm / 128, 4), 256>>>(query, Wq, nullptr, Mm, 0);
    proj_mma_kernel<<<dim3(Bb * SKk / 128, 4), 256>>>(key, Wk, nullptr, SKk, 1);
    proj_mma_kernel<<<dim3(Bb * SKk / 128, 4), 256>>>(value, Wv, nullptr, SKk, 2);

    // Fused banded attention
    attn_kernel<<<dim3(Mm / MT, BKC), 256,
                  ATTN_SMEM_FLOATS * (int)sizeof(float)>>>(pe, span);

    // Output projection
    proj_mma_kernel<<<dim3(Bb * Mm / 128, 4), 256>>>(nullptr, Wo, out, Mm, 3);
}

// round 3
// speedup vs baseline: 2.0944x; 1.8018x over previous
#include <cuda_runtime.h>
#include <cuda_bf16.h>
#include <cstdint>

// Problem constants
#define Bb   8
#define Mm   512
#define Ll   1024
#define Hh   512
#define Kk   8
#define Dd   64
#define SKk  1536           // M + L
#define BKC  64             // B * K
#define SCALE 0.125f

typedef unsigned short ushort_t;

// Scratch (device globals)
__device__ ushort_t gq_h[(size_t)BKC * Mm * Dd];
__device__ ushort_t gq_l[(size_t)BKC * Mm * Dd];
__device__ ushort_t gk_h[(size_t)BKC * SKk * Dd];
__device__ ushort_t gk_l[(size_t)BKC * SKk * Dd];
__device__ ushort_t gv_h[(size_t)BKC * Dd * SKk];   // [bk][d][s]
__device__ ushort_t gv_l[(size_t)BKC * Dd * SKk];
__device__ ushort_t gpe_h[Ll * Dd];                 // [j][d]
__device__ ushort_t gpe_l[Ll * Dd];
__device__ float    g_ctx[(size_t)Bb * Mm * Hh];    // [B, M, K, D]

__device__ __forceinline__ void split_bf(float x, ushort_t& h, ushort_t& l) {
    __nv_bfloat16 hh = __float2bfloat16(x);
    float r = x - __bfloat162float(hh);
    __nv_bfloat16 ll = __float2bfloat16(r);
    h = *reinterpret_cast<ushort_t*>(&hh);
    l = *reinterpret_cast<ushort_t*>(&ll);
}

// ---------------------------------------------------------------------------
// Split-tf32 tensor-core projection GEMM:  Y = X @ W^T  (as round 2)
// sel 0/1: write bf16 hi/lo planes [bk][s][d]; sel 2: transposed [bk][d][s];
// sel 3: fp32 Yout from g_ctx.
// ---------------------------------------------------------------------------
#define PSTR 36

#define MMA_TF32(c, a0, a1, a2, a3, b0, b1)                                   \
    asm volatile(                                                             \
        "mma.sync.aligned.m16n8k8.row.col.f32.tf32.tf32.f32 "                 \
        "{%0,%1,%2,%3},{%4,%5,%6,%7},{%8,%9},{%0,%1,%2,%3};"                  \
        : "+f"(c[0]), "+f"(c[1]), "+f"(c[2]), "+f"(c[3])                      \
        : "r"(a0), "r"(a1), "r"(a2), "r"(a3), "r"(b0), "r"(b1));

#define MMA_BF16(c, a0, a1, a2, a3, b0, b1)                                   \
    asm volatile(                                                             \
        "mma.sync.aligned.m16n8k16.row.col.f32.bf16.bf16.f32 "                \
        "{%0,%1,%2,%3},{%4,%5,%6,%7},{%8,%9},{%0,%1,%2,%3};"                  \
        : "+f"(c[0]), "+f"(c[1]), "+f"(c[2]), "+f"(c[3])                      \
        : "r"(a0), "r"(a1), "r"(a2), "r"(a3), "r"(b0), "r"(b1));

__global__ __launch_bounds__(256) void proj_mma_kernel(
        const float* __restrict__ Xin, const float* __restrict__ W,
        float* __restrict__ Yout, int S, int sel) {
    __shared__ float Xs[128 * PSTR];
    __shared__ float Ws[128 * PSTR];

    const float* __restrict__ X = (sel == 3) ? g_ctx : Xin;

    const int tid  = threadIdx.x;
    const int lane = tid & 31;
    const int wid  = tid >> 5;
    const int warp_m = wid >> 1;
    const int warp_n = wid & 1;
    const int gid = lane >> 2;
    const int tig = lane & 3;
    const int row0 = blockIdx.x * 128;
    const int col0 = blockIdx.y * 128;

    float c[2][8][4];
#pragma unroll
    for (int f = 0; f < 2; f++)
#pragma unroll
        for (int j = 0; j < 8; j++)
#pragma unroll
            for (int t = 0; t < 4; t++) c[f][j][t] = 0.f;

    for (int k0 = 0; k0 < 512; k0 += 32) {
#pragma unroll
        for (int i = 0; i < 4; i++) {
            int f4 = tid + i * 256;
            int r  = f4 >> 3;
            int kq = (f4 & 7) << 2;
            float4 xv = *(const float4*)(X + (size_t)(row0 + r) * 512 + k0 + kq);
            *(float4*)&Xs[r * PSTR + kq] = xv;
            float4 wv = *(const float4*)(W + (size_t)(col0 + r) * 512 + k0 + kq);
            *(float4*)&Ws[r * PSTR + kq] = wv;
        }
        __syncthreads();

#pragma unroll
        for (int kk = 0; kk < 32; kk += 8) {
            uint32_t ahi[2][4], alo[2][4];
#pragma unroll
            for (int f = 0; f < 2; f++) {
                int rbase = warp_m * 32 + f * 16 + gid;
#pragma unroll
                for (int rg = 0; rg < 4; rg++) {
                    int r    = rbase + ((rg & 1) << 3);
                    int kcol = kk + tig + ((rg >> 1) << 2);
                    float x  = Xs[r * PSTR + kcol];
                    uint32_t hb = __float_as_uint(x) & 0xFFFFE000u;
                    ahi[f][rg] = hb;
                    alo[f][rg] = __float_as_uint(x - __uint_as_float(hb));
                }
            }
#pragma unroll
            for (int j = 0; j < 8; j++) {
                int cidx = warp_n * 64 + j * 8 + gid;
                float b0f = Ws[cidx * PSTR + kk + tig];
                float b1f = Ws[cidx * PSTR + kk + tig + 4];
                uint32_t b0h = __float_as_uint(b0f) & 0xFFFFE000u;
                uint32_t b1h = __float_as_uint(b1f) & 0xFFFFE000u;
                uint32_t b0l = __float_as_uint(b0f - __uint_as_float(b0h));
                uint32_t b1l = __float_as_uint(b1f - __uint_as_float(b1h));
#pragma unroll
                for (int f = 0; f < 2; f++) {
                    MMA_TF32(c[f][j], ahi[f][0], ahi[f][1], ahi[f][2], ahi[f][3], b0h, b1h);
                    MMA_TF32(c[f][j], ahi[f][0], ahi[f][1], ahi[f][2], ahi[f][3], b0l, b1l);
                    MMA_TF32(c[f][j], alo[f][0], alo[f][1], alo[f][2], alo[f][3], b0h, b1h);
                }
            }
        }
        __syncthreads();
    }

    // epilogue
#pragma unroll
    for (int f = 0; f < 2; f++) {
        int rloc = warp_m * 32 + f * 16 + gid;
#pragma unroll
        for (int j = 0; j < 8; j++) {
            int cc = col0 + warp_n * 64 + j * 8 + 2 * tig;
#pragma unroll
            for (int h = 0; h < 2; h++) {
                int r = row0 + rloc + h * 8;
                float vx = c[f][j][h * 2], vy = c[f][j][h * 2 + 1];
                if (sel == 3) {
                    *(float2*)(Yout + (size_t)r * 512 + cc) = make_float2(vx, vy);
                } else {
                    int b = r / S, s = r - b * S;
                    int kh = cc >> 6, d = cc & 63;
                    int bk = b * Kk + kh;
                    ushort_t hx, lx, hy, ly;
                    split_bf(vx, hx, lx);
                    split_bf(vy, hy, ly);
                    if (sel == 0) {
                        size_t idx = ((size_t)bk * Mm + s) * Dd + d;
                        *(uint32_t*)&gq_h[idx] = (uint32_t)hx | ((uint32_t)hy << 16);
                        *(uint32_t*)&gq_l[idx] = (uint32_t)lx | ((uint32_t)ly << 16);
                    } else if (sel == 1) {
                        size_t idx = ((size_t)bk * SKk + s) * Dd + d;
                        *(uint32_t*)&gk_h[idx] = (uint32_t)hx | ((uint32_t)hy << 16);
                        *(uint32_t*)&gk_l[idx] = (uint32_t)lx | ((uint32_t)ly << 16);
                    } else {
                        size_t i0 = ((size_t)bk * Dd + d) * SKk + s;
                        size_t i1 = ((size_t)bk * Dd + d + 1) * SKk + s;
                        gv_h[i0] = hx; gv_l[i0] = lx;
                        gv_h[i1] = hy; gv_l[i1] = ly;
                    }
                }
            }
        }
    }
}

// ---------------------------------------------------------------------------
// PE transpose + split prep: gpe[j][d] = pe[d][j]
// ---------------------------------------------------------------------------
__global__ void pe_prep_kernel(const float* __restrict__ pe) {
    int idx = blockIdx.x * 256 + threadIdx.x;
    if (idx < Ll * Dd) {
        int j = idx >> 6, d = idx & 63;
        ushort_t h, l;
        split_bf(pe[d * Ll + j], h, l);
        gpe_h[idx] = h;
        gpe_l[idx] = l;
    }
}

// ---------------------------------------------------------------------------
// MMA banded attention.
// CTA = (bk, 64-query tile). 16 chunks of 64 relative positions.
// Per chunk: QK^T full 64x128 rect (MMA, de-skew scatter to S_rel),
// Q@PE 64x64 (MMA), SIMT online softmax + span mask, P into skewed
// zero-padded plane, AV = P_abs(64x128) @ V_slab^T (MMA).
// ---------------------------------------------------------------------------
// smem arena offsets (in halves unless noted)
#define QH_OFF   0
#define QL_OFF   4608            // 64*72
#define KH_OFF   9216
#define KL_OFF   18432           // KH + 128*72
#define VH_OFF   27648           // KL + 128*72
#define VL_OFF   36352           // VH + 64*136
#define PEH_OFF  45056           // VL + 64*136
#define PEL_OFF  49664           // PEH + 64*72
#define HALVES_END 54272         // PEL + 64*72
// P planes overlay the K region (K consumed before P written)
#define PH_OFF   KH_OFF
#define PL_OFF   (KH_OFF + 8704) // 64*136
// float sections (byte offsets)
#define SREL_B   (HALVES_END * 2)            // 64*68 floats
#define SPE_B    (SREL_B + 64 * 68 * 4)
#define CORR_B   (SPE_B + 64 * 68 * 4)
#define LINV_B   (CORR_B + 64 * 4)
#define ATTN_SMEM_BYTES (LINV_B + 64 * 4)

__global__ __launch_bounds__(256) void attn_mma_kernel(
        const float* __restrict__ span_val) {
    extern __shared__ char smraw[];
    ushort_t* Qh  = (ushort_t*)smraw + QH_OFF;
    ushort_t* Ql  = (ushort_t*)smraw + QL_OFF;
    ushort_t* Kh  = (ushort_t*)smraw + KH_OFF;
    ushort_t* Kl  = (ushort_t*)smraw + KL_OFF;
    ushort_t* Vh  = (ushort_t*)smraw + VH_OFF;
    ushort_t* Vl  = (ushort_t*)smraw + VL_OFF;
    ushort_t* PEh = (ushort_t*)smraw + PEH_OFF;
    ushort_t* PEl = (ushort_t*)smraw + PEL_OFF;
    ushort_t* Ph  = (ushort_t*)smraw + PH_OFF;
    ushort_t* Pl  = (ushort_t*)smraw + PL_OFF;
    float* S_rel  = (float*)(smraw + SREL_B);
    float* S_pe   = (float*)(smraw + SPE_B);
    float* corr_s = (float*)(smraw + CORR_B);
    float* linv_s = (float*)(smraw + LINV_B);

    const int tid  = threadIdx.x;
    const int lane = tid & 31;
    const int wid  = tid >> 5;
    const int gid  = lane >> 2;
    const int tig  = lane & 3;
    const int bk   = blockIdx.y;
    const int i0   = blockIdx.x * 64;
    const int kh   = bk & 7;

    const int m0  = (wid & 3) * 16;
    const int nq0 = (wid >> 2) * 64;
    const int np0 = (wid >> 2) * 32;

    // softmax-phase ownership
    const int srow = tid >> 2;
    const int tg4  = tid & 3;
    const int tbase = tg4 * 16;
    const float spanL = span_val[kh] * 1024.f;

    // Q tile load: [64][64] halves -> [64][72]
    {
        const ushort_t* gqh = gq_h + ((size_t)bk * Mm + i0) * Dd;
        const ushort_t* gql = gq_l + ((size_t)bk * Mm + i0) * Dd;
#pragma unroll
        for (int it = 0; it < 4; it++) {
            int idx = tid + it * 256;          // 0..1023
            int r = idx >> 4, u2 = (idx & 15) * 4;
            *(uint2*)&Qh[r * 72 + u2] = *(const uint2*)&gqh[r * 64 + u2];
            *(uint2*)&Ql[r * 72 + u2] = *(const uint2*)&gql[r * 64 + u2];
        }
    }

    float oacc[4][4];
#pragma unroll
    for (int j = 0; j < 4; j++)
#pragma unroll
        for (int t = 0; t < 4; t++) oacc[j][t] = 0.f;

    float m_run = -1e30f, l_run = 0.f;

    for (int jc = 0; jc < Ll; jc += 64) {
        __syncthreads();
        // ---- load K slab (128x64), V slab (64x128 transposed), PE (64x64)
        {
            const ushort_t* gkh = gk_h + ((size_t)bk * SKk + i0 + jc) * Dd;
            const ushort_t* gkl = gk_l + ((size_t)bk * SKk + i0 + jc) * Dd;
#pragma unroll
            for (int it = 0; it < 8; it++) {
                int idx = tid + it * 256;      // 0..2047
                int r = idx >> 4, u2 = (idx & 15) * 4;
                *(uint2*)&Kh[r * 72 + u2] = *(const uint2*)&gkh[r * 64 + u2];
                *(uint2*)&Kl[r * 72 + u2] = *(const uint2*)&gkl[r * 64 + u2];
            }
            const ushort_t* gvh = gv_h + (size_t)bk * Dd * SKk + i0 + jc;
            const ushort_t* gvl = gv_l + (size_t)bk * Dd * SKk + i0 + jc;
#pragma unroll
            for (int it = 0; it < 4; it++) {
                int idx = tid + it * 256;      // 0..1023
                int d = idx >> 4, q8 = (idx & 15) * 8;
                *(uint4*)&Vh[d * 136 + q8] = *(const uint4*)&gvh[(size_t)d * SKk + q8];
                *(uint4*)&Vl[d * 136 + q8] = *(const uint4*)&gvl[(size_t)d * SKk + q8];
            }
            const ushort_t* gph = gpe_h + (size_t)jc * Dd;
            const ushort_t* gpl = gpe_l + (size_t)jc * Dd;
#pragma unroll
            for (int it = 0; it < 4; it++) {
                int idx = tid + it * 256;
                int r = idx >> 4, u2 = (idx & 15) * 4;
                *(uint2*)&PEh[r * 72 + u2] = *(const uint2*)&gph[r * 64 + u2];
                *(uint2*)&PEl[r * 72 + u2] = *(const uint2*)&gpl[r * 64 + u2];
            }
        }
        __syncthreads();

        // ---- QK^T (64x128) + Q@PE (64x64) MMAs, 3 passes
        float sacc[8][4], pacc[4][4];
#pragma unroll
        for (int j = 0; j < 8; j++)
#pragma unroll
            for (int t = 0; t < 4; t++) sacc[j][t] = 0.f;
#pragma unroll
        for (int j = 0; j < 4; j++)
#pragma unroll
            for (int t = 0; t < 4; t++) pacc[j][t] = 0.f;

#pragma unroll
        for (int pass = 0; pass < 3; pass++) {
            const ushort_t* Ap = (pass == 2) ? Ql : Qh;
            const ushort_t* Bp = (pass == 1) ? Kl : Kh;
            const ushort_t* Pp = (pass == 1) ? PEl : PEh;
#pragma unroll
            for (int k0 = 0; k0 < 64; k0 += 16) {
                uint32_t a0 = *(const uint32_t*)&Ap[(m0 + gid) * 72 + k0 + 2 * tig];
                uint32_t a1 = *(const uint32_t*)&Ap[(m0 + gid + 8) * 72 + k0 + 2 * tig];
                uint32_t a2 = *(const uint32_t*)&Ap[(m0 + gid) * 72 + k0 + 2 * tig + 8];
                uint32_t a3 = *(const uint32_t*)&Ap[(m0 + gid + 8) * 72 + k0 + 2 * tig + 8];
#pragma unroll
                for (int j = 0; j < 8; j++) {
                    uint32_t b0 = *(const uint32_t*)&Bp[(nq0 + 8 * j + gid) * 72 + k0 + 2 * tig];
                    uint32_t b1 = *(const uint32_t*)&Bp[(nq0 + 8 * j + gid) * 72 + k0 + 2 * tig + 8];
                    MMA_BF16(sacc[j], a0, a1, a2, a3, b0, b1);
                }
#pragma unroll
                for (int j = 0; j < 4; j++) {
                    uint32_t b0 = *(const uint32_t*)&Pp[(np0 + 8 * j + gid) * 72 + k0 + 2 * tig];
                    uint32_t b1 = *(const uint32_t*)&Pp[(np0 + 8 * j + gid) * 72 + k0 + 2 * tig + 8];
                    MMA_BF16(pacc[j], a0, a1, a2, a3, b0, b1);
                }
            }
        }

        // scatter QK rect -> de-skewed S_rel[i][col-row]
#pragma unroll
        for (int j = 0; j < 8; j++) {
            int col = nq0 + 8 * j + 2 * tig;
            int r0 = m0 + gid, r1 = r0 + 8;
            int t00 = col - r0, t10 = col - r1;
            if ((unsigned)t00 < 64u)      S_rel[r0 * 68 + t00]     = sacc[j][0];
            if ((unsigned)(t00 + 1) < 64u) S_rel[r0 * 68 + t00 + 1] = sacc[j][1];
            if ((unsigned)t10 < 64u)      S_rel[r1 * 68 + t10]     = sacc[j][2];
            if ((unsigned)(t10 + 1) < 64u) S_rel[r1 * 68 + t10 + 1] = sacc[j][3];
        }
#pragma unroll
        for (int j = 0; j < 4; j++) {
            int col = np0 + 8 * j + 2 * tig;
            S_pe[(m0 + gid) * 68 + col]     = pacc[j][0];
            S_pe[(m0 + gid) * 68 + col + 1] = pacc[j][1];
            S_pe[(m0 + gid + 8) * 68 + col]     = pacc[j][2];
            S_pe[(m0 + gid + 8) * 68 + col + 1] = pacc[j][3];
        }
        __syncthreads();

        // ---- online softmax (4 threads per row, 16 t each)
        {
            float s[16];
            float mloc = -1e30f;
#pragma unroll
            for (int e = 0; e < 16; e++) {
                s[e] = (S_rel[srow * 68 + tbase + e] + S_pe[srow * 68 + tbase + e]) * SCALE;
                mloc = fmaxf(mloc, s[e]);
            }
            mloc = fmaxf(mloc, __shfl_xor_sync(0xFFFFFFFFu, mloc, 1));
            mloc = fmaxf(mloc, __shfl_xor_sync(0xFFFFFFFFu, mloc, 2));
            float m_new = fmaxf(m_run, mloc);
            float corr  = __expf(m_run - m_new);
            l_run *= corr;
            float p[16], psum = 0.f;
#pragma unroll
            for (int e = 0; e < 16; e++) { p[e] = __expf(s[e] - m_new); psum += p[e]; }
            psum += __shfl_xor_sync(0xFFFFFFFFu, psum, 1);
            psum += __shfl_xor_sync(0xFFFFFFFFu, psum, 2);
            l_run += psum;
            m_run = m_new;
            if (tg4 == 0) corr_s[srow] = corr;

            // masked P into skewed plane + zero complement
#pragma unroll
            for (int e = 0; e < 16; e++) {
                int t = tbase + e;
                float jj = (float)(jc + t);
                float mk = fminf(1.f, fmaxf(0.f, (jj - 1023.f + spanL) * (1.f / 32.f) + 1.f));
                float pm = p[e] * mk;
                ushort_t hh, ll;
                split_bf(pm, hh, ll);
                int u = srow + t;
                Ph[srow * 136 + u] = hh;
                Pl[srow * 136 + u] = ll;
                int cz = t;                     // complement slot
                int uz = (cz < srow) ? cz : cz + 64;
                Ph[srow * 136 + uz] = 0;
                Pl[srow * 136 + uz] = 0;
            }
        }
        __syncthreads();

        // ---- AV: oacc = oacc*corr + P_abs @ V^T
        {
            float cA = corr_s[m0 + gid], cB = corr_s[m0 + gid + 8];
#pragma unroll
            for (int j = 0; j < 4; j++) {
                oacc[j][0] *= cA; oacc[j][1] *= cA;
                oacc[j][2] *= cB; oacc[j][3] *= cB;
            }
#pragma unroll
            for (int pass = 0; pass < 3; pass++) {
                const ushort_t* Ap = (pass == 2) ? Pl : Ph;
                const ushort_t* Bp = (pass == 1) ? Vl : Vh;
#pragma unroll
                for (int k0 = 0; k0 < 128; k0 += 16) {
                    uint32_t a0 = *(const uint32_t*)&Ap[(m0 + gid) * 136 + k0 + 2 * tig];
                    uint32_t a1 = *(const uint32_t*)&Ap[(m0 + gid + 8) * 136 + k0 + 2 * tig];
                    uint32_t a2 = *(const uint32_t*)&Ap[(m0 + gid) * 136 + k0 + 2 * tig + 8];
                    uint32_t a3 = *(const uint32_t*)&Ap[(m0 + gid + 8) * 136 + k0 + 2 * tig + 8];
#pragma unroll
                    for (int j = 0; j < 4; j++) {
                        uint32_t b0 = *(const uint32_t*)&Bp[(np0 + 8 * j + gid) * 136 + k0 + 2 * tig];
                        uint32_t b1 = *(const uint32_t*)&Bp[(np0 + 8 * j + gid) * 136 + k0 + 2 * tig + 8];
                        MMA_BF16(oacc[j], a0, a1, a2, a3, b0, b1);
                    }
                }
            }
        }
    }

    __syncthreads();
    if (tg4 == 0) linv_s[srow] = 1.f / l_run;
    __syncthreads();

    // epilogue: g_ctx[b][i0+row][kh][d]
    {
        float lA = linv_s[m0 + gid], lB = linv_s[m0 + gid + 8];
        int b = bk >> 3;
        int r0 = i0 + m0 + gid;
#pragma unroll
        for (int j = 0; j < 4; j++) {
            int col = np0 + 8 * j + 2 * tig;
            float* p0 = g_ctx + ((size_t)(b * Mm + r0) * Kk + kh) * Dd + col;
            float* p1 = g_ctx + ((size_t)(b * Mm + r0 + 8) * Kk + kh) * Dd + col;
            *(float2*)p0 = make_float2(oacc[j][0] * lA, oacc[j][1] * lA);
            *(float2*)p1 = make_float2(oacc[j][2] * lB, oacc[j][3] * lB);
        }
    }
}

// ---------------------------------------------------------------------------
extern "C" void kernel_launch(void* const* d_in, const int* in_sizes, int n_in,
                              void* d_out, int out_size) {
    const float* query = (const float*)d_in[0];
    const float* key   = (const float*)d_in[1];
    const float* value = (const float*)d_in[2];
    const float* pe    = (const float*)d_in[3];
    const float* Wq    = (const float*)d_in[4];
    const float* Wk    = (const float*)d_in[5];
    const float* Wv    = (const float*)d_in[6];
    const float* Wo    = (const float*)d_in[7];
    const float* span  = (const float*)d_in[8];
    float* out = (float*)d_out;

    cudaFuncSetAttribute(attn_mma_kernel,
                         cudaFuncAttributeMaxDynamicSharedMemorySize,
                         ATTN_SMEM_BYTES);

    proj_mma_kernel<<<dim3(Bb * Mm / 128, 4), 256>>>(query, Wq, nullptr, Mm, 0);
    proj_mma_kernel<<<dim3(Bb * SKk / 128, 4), 256>>>(key, Wk, nullptr, SKk, 1);
    proj_mma_kernel<<<dim3(Bb * SKk / 128, 4), 256>>>(value, Wv, nullptr, SKk, 2);
    pe_prep_kernel<<<(Ll * Dd + 255) / 256, 256>>>(pe);

    attn_mma_kernel<<<dim3(Mm / 64, BKC), 256, ATTN_SMEM_BYTES>>>(span);

    proj_mma_kernel<<<dim3(Bb * Mm / 128, 4), 256>>>(nullptr, Wo, out, Mm, 3);
}

// round 4
// speedup vs baseline: 2.2847x; 1.0909x over previous
#include <cuda_runtime.h>
#include <cuda_bf16.h>
#include <cstdint>

// Problem constants
#define Bb   8
#define Mm   512
#define Ll   1024
#define Hh   512
#define Kk   8
#define Dd   64
#define SKk  1536           // M + L
#define BKC  64             // B * K
#define SCALE 0.125f

// Scratch (device globals)
__device__ float gq[(size_t)BKC * Mm * Dd];      // [bk][s][d]
__device__ float gk[(size_t)BKC * SKk * Dd];     // [bk][s][d]
__device__ float gv[(size_t)BKC * Dd * SKk];     // [bk][d][s]  (transposed)
__device__ float gpe[Ll * Dd];                   // [j][d]
__device__ float g_ctx[(size_t)Bb * Mm * Hh];    // [B, M, K, D]

__device__ __forceinline__ float to_tf32(float x) {
    uint32_t r;
    asm("cvt.rna.tf32.f32 %0, %1;" : "=r"(r) : "f"(x));
    return __uint_as_float(r);
}

#define MMA_TF32(c, a0, a1, a2, a3, b0, b1)                                   \
    asm volatile(                                                             \
        "mma.sync.aligned.m16n8k8.row.col.f32.tf32.tf32.f32 "                 \
        "{%0,%1,%2,%3},{%4,%5,%6,%7},{%8,%9},{%0,%1,%2,%3};"                  \
        : "+f"(c[0]), "+f"(c[1]), "+f"(c[2]), "+f"(c[3])                      \
        : "r"(a0), "r"(a1), "r"(a2), "r"(a3), "r"(b0), "r"(b1));

// ---------------------------------------------------------------------------
// Split-tf32 tensor-core projection GEMM:  Y = X @ W^T   (3-pass, accurate)
// sel 0: gq [bk][s][d];  1: gk;  2: gv transposed [bk][d][s];
// sel 3: fp32 Yout from g_ctx.
// All q/k/v outputs are tf32-rounded at store time.
// ---------------------------------------------------------------------------
#define PJSTR 36

__global__ __launch_bounds__(256) void proj_mma_kernel(
        const float* __restrict__ Xin, const float* __restrict__ W,
        float* __restrict__ Yout, int S, int sel) {
    __shared__ float Xs[128 * PJSTR];
    __shared__ float Ws[128 * PJSTR];

    const float* __restrict__ X = (sel == 3) ? g_ctx : Xin;

    const int tid  = threadIdx.x;
    const int lane = tid & 31;
    const int wid  = tid >> 5;
    const int warp_m = wid >> 1;
    const int warp_n = wid & 1;
    const int gid = lane >> 2;
    const int tig = lane & 3;
    const int row0 = blockIdx.x * 128;
    const int col0 = blockIdx.y * 128;

    float c[2][8][4];
#pragma unroll
    for (int f = 0; f < 2; f++)
#pragma unroll
        for (int j = 0; j < 8; j++)
#pragma unroll
            for (int t = 0; t < 4; t++) c[f][j][t] = 0.f;

    for (int k0 = 0; k0 < 512; k0 += 32) {
#pragma unroll
        for (int i = 0; i < 4; i++) {
            int f4 = tid + i * 256;
            int r  = f4 >> 3;
            int kq = (f4 & 7) << 2;
            float4 xv = *(const float4*)(X + (size_t)(row0 + r) * 512 + k0 + kq);
            *(float4*)&Xs[r * PJSTR + kq] = xv;
            float4 wv = *(const float4*)(W + (size_t)(col0 + r) * 512 + k0 + kq);
            *(float4*)&Ws[r * PJSTR + kq] = wv;
        }
        __syncthreads();

#pragma unroll
        for (int kk = 0; kk < 32; kk += 8) {
            uint32_t ahi[2][4], alo[2][4];
#pragma unroll
            for (int f = 0; f < 2; f++) {
                int rbase = warp_m * 32 + f * 16 + gid;
#pragma unroll
                for (int rg = 0; rg < 4; rg++) {
                    int r    = rbase + ((rg & 1) << 3);
                    int kcol = kk + tig + ((rg >> 1) << 2);
                    float x  = Xs[r * PJSTR + kcol];
                    uint32_t hb = __float_as_uint(x) & 0xFFFFE000u;
                    ahi[f][rg] = hb;
                    alo[f][rg] = __float_as_uint(x - __uint_as_float(hb));
                }
            }
#pragma unroll
            for (int j = 0; j < 8; j++) {
                int cidx = warp_n * 64 + j * 8 + gid;
                float b0f = Ws[cidx * PJSTR + kk + tig];
                float b1f = Ws[cidx * PJSTR + kk + tig + 4];
                uint32_t b0h = __float_as_uint(b0f) & 0xFFFFE000u;
                uint32_t b1h = __float_as_uint(b1f) & 0xFFFFE000u;
                uint32_t b0l = __float_as_uint(b0f - __uint_as_float(b0h));
                uint32_t b1l = __float_as_uint(b1f - __uint_as_float(b1h));
#pragma unroll
                for (int f = 0; f < 2; f++) {
                    MMA_TF32(c[f][j], ahi[f][0], ahi[f][1], ahi[f][2], ahi[f][3], b0h, b1h);
                    MMA_TF32(c[f][j], ahi[f][0], ahi[f][1], ahi[f][2], ahi[f][3], b0l, b1l);
                    MMA_TF32(c[f][j], alo[f][0], alo[f][1], alo[f][2], alo[f][3], b0h, b1h);
                }
            }
        }
        __syncthreads();
    }

    // epilogue
#pragma unroll
    for (int f = 0; f < 2; f++) {
        int rloc = warp_m * 32 + f * 16 + gid;
#pragma unroll
        for (int j = 0; j < 8; j++) {
            int cc = col0 + warp_n * 64 + j * 8 + 2 * tig;
#pragma unroll
            for (int h = 0; h < 2; h++) {
                int r = row0 + rloc + h * 8;
                float vx = c[f][j][h * 2], vy = c[f][j][h * 2 + 1];
                if (sel == 3) {
                    *(float2*)(Yout + (size_t)r * 512 + cc) = make_float2(vx, vy);
                } else {
                    int b = r / S, s = r - b * S;
                    int kh = cc >> 6, d = cc & 63;
                    int bk = b * Kk + kh;
                    float tx = to_tf32(vx), ty = to_tf32(vy);
                    if (sel == 0) {
                        *(float2*)&gq[((size_t)bk * Mm + s) * Dd + d] = make_float2(tx, ty);
                    } else if (sel == 1) {
                        *(float2*)&gk[((size_t)bk * SKk + s) * Dd + d] = make_float2(tx, ty);
                    } else {
                        gv[((size_t)bk * Dd + d) * SKk + s]     = tx;
                        gv[((size_t)bk * Dd + d + 1) * SKk + s] = ty;
                    }
                }
            }
        }
    }
}

// ---------------------------------------------------------------------------
// PE transpose prep: gpe[j][d] = tf32(pe[d][j])
// ---------------------------------------------------------------------------
__global__ void pe_prep_kernel(const float* __restrict__ pe) {
    int idx = blockIdx.x * 256 + threadIdx.x;
    if (idx < Ll * Dd) {
        int j = idx >> 6, d = idx & 63;
        gpe[idx] = to_tf32(pe[d * Ll + j]);
    }
}

// ---------------------------------------------------------------------------
// Single-pass tf32 MMA banded attention.
// CTA = (bk, 64-query tile). 16 chunks of 64 relative positions.
// QK^T 64x128 rect -> de-skew scatter; Q@PE 64x64; SIMT online softmax;
// masked P (tf32-rounded) into skewed zero-padded plane; AV = P(64x128)@V^T.
// ---------------------------------------------------------------------------
#define QSTR 68
#define KSTR 68
#define VSTR 132
#define PSTR2 132
// smem float offsets
#define OFF_Q    0
#define OFF_K    (OFF_Q + 64 * QSTR)       // 4352
#define OFF_V    (OFF_K + 128 * KSTR)      // +8704
#define OFF_PE   (OFF_V + 64 * VSTR)       // +8448
#define OFF_SREL (OFF_PE + 64 * QSTR)
#define OFF_SPE  (OFF_SREL + 64 * QSTR)
#define OFF_CORR (OFF_SPE + 64 * QSTR)
#define OFF_LINV (OFF_CORR + 64)
#define ATTN_SMEM_FLOATS (OFF_LINV + 64)
#define OFF_P    OFF_K                      // P (64*132) overlays K (128*68)

__global__ __launch_bounds__(256) void attn_mma_kernel(
        const float* __restrict__ span_val) {
    extern __shared__ float sm[];
    float* Qs   = sm + OFF_Q;
    float* Ks   = sm + OFF_K;
    float* Vs   = sm + OFF_V;
    float* PEs  = sm + OFF_PE;
    float* Srel = sm + OFF_SREL;
    float* Spe  = sm + OFF_SPE;
    float* corr_s = sm + OFF_CORR;
    float* linv_s = sm + OFF_LINV;
    float* Ps   = sm + OFF_P;

    const uint32_t* Qu  = (const uint32_t*)Qs;
    const uint32_t* Ku  = (const uint32_t*)Ks;
    const uint32_t* Vu  = (const uint32_t*)Vs;
    const uint32_t* PEu = (const uint32_t*)PEs;
    const uint32_t* Pu  = (const uint32_t*)Ps;

    const int tid  = threadIdx.x;
    const int lane = tid & 31;
    const int wid  = tid >> 5;
    const int gid  = lane >> 2;
    const int tig  = lane & 3;
    const int bk   = blockIdx.y;
    const int i0   = blockIdx.x * 64;
    const int kh   = bk & 7;

    const int m0  = (wid & 3) * 16;
    const int nq0 = (wid >> 2) * 64;
    const int np0 = (wid >> 2) * 32;

    const int srow = tid >> 2;
    const int tg4  = tid & 3;
    const int tbase = tg4 * 16;
    const float spanL = span_val[kh] * 1024.f;

    // Q tile: [64][64] -> [64][QSTR]
    {
        const float* gqp = gq + ((size_t)bk * Mm + i0) * Dd;
#pragma unroll
        for (int it = 0; it < 4; it++) {
            int idx = tid + it * 256;
            int r = idx >> 4, c4 = (idx & 15) << 2;
            *(float4*)&Qs[r * QSTR + c4] = *(const float4*)(gqp + (size_t)r * Dd + c4);
        }
    }

    float oacc[4][4];
#pragma unroll
    for (int j = 0; j < 4; j++)
#pragma unroll
        for (int t = 0; t < 4; t++) oacc[j][t] = 0.f;

    float m_run = -1e30f, l_run = 0.f;

    for (int jc = 0; jc < Ll; jc += 64) {
        __syncthreads();
        // stage K (128x64), V (64 d x 128 u), PE (64x64)
        {
            const float* gkp = gk + ((size_t)bk * SKk + i0 + jc) * Dd;
#pragma unroll
            for (int it = 0; it < 8; it++) {
                int idx = tid + it * 256;          // 0..2047
                int r = idx >> 4, c4 = (idx & 15) << 2;
                *(float4*)&Ks[r * KSTR + c4] = *(const float4*)(gkp + (size_t)r * Dd + c4);
            }
            const float* gvp = gv + (size_t)bk * Dd * SKk + i0 + jc;
#pragma unroll
            for (int it = 0; it < 8; it++) {
                int idx = tid + it * 256;          // 0..2047
                int d = idx >> 5, c4 = (idx & 31) << 2;
                *(float4*)&Vs[d * VSTR + c4] = *(const float4*)(gvp + (size_t)d * SKk + c4);
            }
            const float* gpp = gpe + (size_t)jc * Dd;
#pragma unroll
            for (int it = 0; it < 4; it++) {
                int idx = tid + it * 256;
                int r = idx >> 4, c4 = (idx & 15) << 2;
                *(float4*)&PEs[r * QSTR + c4] = *(const float4*)(gpp + (size_t)r * Dd + c4);
            }
        }
        __syncthreads();

        // ---- QK^T (64x128) + Q@PE (64x64), single-pass tf32
        float sacc[8][4], pacc[4][4];
#pragma unroll
        for (int j = 0; j < 8; j++)
#pragma unroll
            for (int t = 0; t < 4; t++) sacc[j][t] = 0.f;
#pragma unroll
        for (int j = 0; j < 4; j++)
#pragma unroll
            for (int t = 0; t < 4; t++) pacc[j][t] = 0.f;

#pragma unroll
        for (int k0 = 0; k0 < 64; k0 += 8) {
            int ar = (m0 + gid) * QSTR + k0 + tig;
            uint32_t a0 = Qu[ar];
            uint32_t a1 = Qu[ar + 8 * QSTR];
            uint32_t a2 = Qu[ar + 4];
            uint32_t a3 = Qu[ar + 8 * QSTR + 4];
#pragma unroll
            for (int j = 0; j < 8; j++) {
                int br = (nq0 + 8 * j + gid) * KSTR + k0 + tig;
                MMA_TF32(sacc[j], a0, a1, a2, a3, Ku[br], Ku[br + 4]);
            }
#pragma unroll
            for (int j = 0; j < 4; j++) {
                int br = (np0 + 8 * j + gid) * QSTR + k0 + tig;
                MMA_TF32(pacc[j], a0, a1, a2, a3, PEu[br], PEu[br + 4]);
            }
        }

        // scatter QK rect -> de-skewed Srel[i][col-row]
#pragma unroll
        for (int j = 0; j < 8; j++) {
            int col = nq0 + 8 * j + 2 * tig;
            int r0 = m0 + gid, r1 = r0 + 8;
            int t00 = col - r0, t10 = col - r1;
            if ((unsigned)t00 < 64u)       Srel[r0 * QSTR + t00]     = sacc[j][0];
            if ((unsigned)(t00 + 1) < 64u) Srel[r0 * QSTR + t00 + 1] = sacc[j][1];
            if ((unsigned)t10 < 64u)       Srel[r1 * QSTR + t10]     = sacc[j][2];
            if ((unsigned)(t10 + 1) < 64u) Srel[r1 * QSTR + t10 + 1] = sacc[j][3];
        }
#pragma unroll
        for (int j = 0; j < 4; j++) {
            int col = np0 + 8 * j + 2 * tig;
            Spe[(m0 + gid) * QSTR + col]     = pacc[j][0];
            Spe[(m0 + gid) * QSTR + col + 1] = pacc[j][1];
            Spe[(m0 + gid + 8) * QSTR + col]     = pacc[j][2];
            Spe[(m0 + gid + 8) * QSTR + col + 1] = pacc[j][3];
        }
        __syncthreads();

        // ---- online softmax (4 threads per row, 16 t each)
        {
            float s[16];
            float mloc = -1e30f;
#pragma unroll
            for (int e = 0; e < 16; e++) {
                s[e] = (Srel[srow * QSTR + tbase + e] + Spe[srow * QSTR + tbase + e]) * SCALE;
                mloc = fmaxf(mloc, s[e]);
            }
            mloc = fmaxf(mloc, __shfl_xor_sync(0xFFFFFFFFu, mloc, 1));
            mloc = fmaxf(mloc, __shfl_xor_sync(0xFFFFFFFFu, mloc, 2));
            float m_new = fmaxf(m_run, mloc);
            float corr  = __expf(m_run - m_new);
            l_run *= corr;
            float p[16], psum = 0.f;
#pragma unroll
            for (int e = 0; e < 16; e++) { p[e] = __expf(s[e] - m_new); psum += p[e]; }
            psum += __shfl_xor_sync(0xFFFFFFFFu, psum, 1);
            psum += __shfl_xor_sync(0xFFFFFFFFu, psum, 2);
            l_run += psum;
            m_run = m_new;
            if (tg4 == 0) corr_s[srow] = corr;

            // masked P into skewed plane + zero complement
#pragma unroll
            for (int e = 0; e < 16; e++) {
                int t = tbase + e;
                float jj = (float)(jc + t);
                float mk = fminf(1.f, fmaxf(0.f, (jj - 1023.f + spanL) * (1.f / 32.f) + 1.f));
                float pm = to_tf32(p[e] * mk);
                int u = srow + t;
                Ps[srow * PSTR2 + u] = pm;
                int uz = (t < srow) ? t : t + 64;
                Ps[srow * PSTR2 + uz] = 0.f;
            }
        }
        __syncthreads();

        // ---- AV: oacc = oacc*corr + P_abs @ V^T   (single-pass tf32)
        {
            float cA = corr_s[m0 + gid], cB = corr_s[m0 + gid + 8];
#pragma unroll
            for (int j = 0; j < 4; j++) {
                oacc[j][0] *= cA; oacc[j][1] *= cA;
                oacc[j][2] *= cB; oacc[j][3] *= cB;
            }
#pragma unroll
            for (int k0 = 0; k0 < 128; k0 += 8) {
                int ar = (m0 + gid) * PSTR2 + k0 + tig;
                uint32_t a0 = Pu[ar];
                uint32_t a1 = Pu[ar + 8 * PSTR2];
                uint32_t a2 = Pu[ar + 4];
                uint32_t a3 = Pu[ar + 8 * PSTR2 + 4];
#pragma unroll
                for (int j = 0; j < 4; j++) {
                    int br = (np0 + 8 * j + gid) * VSTR + k0 + tig;
                    MMA_TF32(oacc[j], a0, a1, a2, a3, Vu[br], Vu[br + 4]);
                }
            }
        }
    }

    __syncthreads();
    if (tg4 == 0) linv_s[srow] = 1.f / l_run;
    __syncthreads();

    // epilogue: g_ctx[b][i0+row][kh][d]
    {
        float lA = linv_s[m0 + gid], lB = linv_s[m0 + gid + 8];
        int b = bk >> 3;
        int r0 = i0 + m0 + gid;
#pragma unroll
        for (int j = 0; j < 4; j++) {
            int col = np0 + 8 * j + 2 * tig;
            float* p0 = g_ctx + ((size_t)(b * Mm + r0) * Kk + kh) * Dd + col;
            float* p1 = g_ctx + ((size_t)(b * Mm + r0 + 8) * Kk + kh) * Dd + col;
            *(float2*)p0 = make_float2(oacc[j][0] * lA, oacc[j][1] * lA);
            *(float2*)p1 = make_float2(oacc[j][2] * lB, oacc[j][3] * lB);
        }
    }
}

// ---------------------------------------------------------------------------
extern "C" void kernel_launch(void* const* d_in, const int* in_sizes, int n_in,
                              void* d_out, int out_size) {
    const float* query = (const float*)d_in[0];
    const float* key   = (const float*)d_in[1];
    const float* value = (const float*)d_in[2];
    const float* pe    = (const float*)d_in[3];
    const float* Wq    = (const float*)d_in[4];
    const float* Wk    = (const float*)d_in[5];
    const float* Wv    = (const float*)d_in[6];
    const float* Wo    = (const float*)d_in[7];
    const float* span  = (const float*)d_in[8];
    float* out = (float*)d_out;

    cudaFuncSetAttribute(attn_mma_kernel,
                         cudaFuncAttributeMaxDynamicSharedMemorySize,
                         ATTN_SMEM_FLOATS * (int)sizeof(float));

    proj_mma_kernel<<<dim3(Bb * Mm / 128, 4), 256>>>(query, Wq, nullptr, Mm, 0);
    proj_mma_kernel<<<dim3(Bb * SKk / 128, 4), 256>>>(key, Wk, nullptr, SKk, 1);
    proj_mma_kernel<<<dim3(Bb * SKk / 128, 4), 256>>>(value, Wv, nullptr, SKk, 2);
    pe_prep_kernel<<<(Ll * Dd + 255) / 256, 256>>>(pe);

    attn_mma_kernel<<<dim3(Mm / 64, BKC), 256,
                      ATTN_SMEM_FLOATS * (int)sizeof(float)>>>(span);

    proj_mma_kernel<<<dim3(Bb * Mm / 128, 4), 256>>>(nullptr, Wo, out, Mm, 3);
}

// round 5
// speedup vs baseline: 2.9972x; 1.3118x over previous
#include <cuda_runtime.h>
#include <cuda_bf16.h>
#include <cstdint>

// Problem constants
#define Bb   8
#define Mm   512
#define Ll   1024
#define Hh   512
#define Kk   8
#define Dd   64
#define SKk  1536           // M + L
#define BKC  64             // B * K
#define SCALE 0.125f

// Scratch (device globals)
__device__ float gq[(size_t)BKC * Mm * Dd];      // [bk][s][d]
__device__ float gk[(size_t)BKC * SKk * Dd];     // [bk][s][d]
__device__ float gv[(size_t)BKC * Dd * SKk];     // [bk][d][s]  (transposed)
__device__ float gpe[Ll * Dd];                   // [j][d]
__device__ float g_ctx[(size_t)Bb * Mm * Hh];    // [B, M, K, D]

__device__ __forceinline__ float to_tf32(float x) {
    uint32_t r;
    asm("cvt.rna.tf32.f32 %0, %1;" : "=r"(r) : "f"(x));
    return __uint_as_float(r);
}
__device__ __forceinline__ uint32_t rna_u(float x) {
    uint32_t r;
    asm("cvt.rna.tf32.f32 %0, %1;" : "=r"(r) : "f"(x));
    return r;
}

#define MMA_TF32(c, a0, a1, a2, a3, b0, b1)                                   \
    asm volatile(                                                             \
        "mma.sync.aligned.m16n8k8.row.col.f32.tf32.tf32.f32 "                 \
        "{%0,%1,%2,%3},{%4,%5,%6,%7},{%8,%9},{%0,%1,%2,%3};"                  \
        : "+f"(c[0]), "+f"(c[1]), "+f"(c[2]), "+f"(c[3])                      \
        : "r"(a0), "r"(a1), "r"(a2), "r"(a3), "r"(b0), "r"(b1));

#define PJSTR 36

// ---------------------------------------------------------------------------
// Single-pass tf32 QKV projection GEMM: Y = X @ W^T, head-split stores.
// sel 0: gq [bk][s][d]; 1: gk; 2: gv transposed [bk][d][s].
// ---------------------------------------------------------------------------
__global__ __launch_bounds__(256) void proj_qkv_kernel(
        const float* __restrict__ X, const float* __restrict__ W,
        int S, int sel) {
    __shared__ float Xs[128 * PJSTR];
    __shared__ float Ws[128 * PJSTR];

    const int tid  = threadIdx.x;
    const int lane = tid & 31;
    const int wid  = tid >> 5;
    const int warp_m = wid >> 1;
    const int warp_n = wid & 1;
    const int gid = lane >> 2;
    const int tig = lane & 3;
    const int row0 = blockIdx.x * 128;
    const int col0 = blockIdx.y * 128;

    float c[2][8][4];
#pragma unroll
    for (int f = 0; f < 2; f++)
#pragma unroll
        for (int j = 0; j < 8; j++)
#pragma unroll
            for (int t = 0; t < 4; t++) c[f][j][t] = 0.f;

    for (int k0 = 0; k0 < 512; k0 += 32) {
#pragma unroll
        for (int i = 0; i < 4; i++) {
            int f4 = tid + i * 256;
            int r  = f4 >> 3;
            int kq = (f4 & 7) << 2;
            float4 xv = *(const float4*)(X + (size_t)(row0 + r) * 512 + k0 + kq);
            *(float4*)&Xs[r * PJSTR + kq] = xv;
            float4 wv = *(const float4*)(W + (size_t)(col0 + r) * 512 + k0 + kq);
            *(float4*)&Ws[r * PJSTR + kq] = wv;
        }
        __syncthreads();

#pragma unroll
        for (int kk = 0; kk < 32; kk += 8) {
            uint32_t a[2][4];
#pragma unroll
            for (int f = 0; f < 2; f++) {
                int rbase = warp_m * 32 + f * 16 + gid;
#pragma unroll
                for (int rg = 0; rg < 4; rg++) {
                    int r    = rbase + ((rg & 1) << 3);
                    int kcol = kk + tig + ((rg >> 1) << 2);
                    a[f][rg] = rna_u(Xs[r * PJSTR + kcol]);
                }
            }
#pragma unroll
            for (int j = 0; j < 8; j++) {
                int cidx = warp_n * 64 + j * 8 + gid;
                uint32_t b0 = rna_u(Ws[cidx * PJSTR + kk + tig]);
                uint32_t b1 = rna_u(Ws[cidx * PJSTR + kk + tig + 4]);
#pragma unroll
                for (int f = 0; f < 2; f++)
                    MMA_TF32(c[f][j], a[f][0], a[f][1], a[f][2], a[f][3], b0, b1);
            }
        }
        __syncthreads();
    }

#pragma unroll
    for (int f = 0; f < 2; f++) {
        int rloc = warp_m * 32 + f * 16 + gid;
#pragma unroll
        for (int j = 0; j < 8; j++) {
            int cc = col0 + warp_n * 64 + j * 8 + 2 * tig;
#pragma unroll
            for (int h = 0; h < 2; h++) {
                int r = row0 + rloc + h * 8;
                int b = r / S, s = r - b * S;
                int kh = cc >> 6, d = cc & 63;
                int bk = b * Kk + kh;
                float tx = to_tf32(c[f][j][h * 2]);
                float ty = to_tf32(c[f][j][h * 2 + 1]);
                if (sel == 0) {
                    *(float2*)&gq[((size_t)bk * Mm + s) * Dd + d] = make_float2(tx, ty);
                } else if (sel == 1) {
                    *(float2*)&gk[((size_t)bk * SKk + s) * Dd + d] = make_float2(tx, ty);
                } else {
                    gv[((size_t)bk * Dd + d) * SKk + s]     = tx;
                    gv[((size_t)bk * Dd + d + 1) * SKk + s] = ty;
                }
            }
        }
    }
}

// ---------------------------------------------------------------------------
// 3-pass split-tf32 output GEMM: out = g_ctx @ Wo^T  (precision anchor)
// ---------------------------------------------------------------------------
__global__ __launch_bounds__(256) void proj_out_kernel(
        const float* __restrict__ W, float* __restrict__ Yout) {
    __shared__ float Xs[128 * PJSTR];
    __shared__ float Ws[128 * PJSTR];

    const int tid  = threadIdx.x;
    const int lane = tid & 31;
    const int wid  = tid >> 5;
    const int warp_m = wid >> 1;
    const int warp_n = wid & 1;
    const int gid = lane >> 2;
    const int tig = lane & 3;
    const int row0 = blockIdx.x * 128;
    const int col0 = blockIdx.y * 128;

    float c[2][8][4];
#pragma unroll
    for (int f = 0; f < 2; f++)
#pragma unroll
        for (int j = 0; j < 8; j++)
#pragma unroll
            for (int t = 0; t < 4; t++) c[f][j][t] = 0.f;

    for (int k0 = 0; k0 < 512; k0 += 32) {
#pragma unroll
        for (int i = 0; i < 4; i++) {
            int f4 = tid + i * 256;
            int r  = f4 >> 3;
            int kq = (f4 & 7) << 2;
            float4 xv = *(const float4*)(g_ctx + (size_t)(row0 + r) * 512 + k0 + kq);
            *(float4*)&Xs[r * PJSTR + kq] = xv;
            float4 wv = *(const float4*)(W + (size_t)(col0 + r) * 512 + k0 + kq);
            *(float4*)&Ws[r * PJSTR + kq] = wv;
        }
        __syncthreads();

#pragma unroll
        for (int kk = 0; kk < 32; kk += 8) {
            uint32_t ahi[2][4], alo[2][4];
#pragma unroll
            for (int f = 0; f < 2; f++) {
                int rbase = warp_m * 32 + f * 16 + gid;
#pragma unroll
                for (int rg = 0; rg < 4; rg++) {
                    int r    = rbase + ((rg & 1) << 3);
                    int kcol = kk + tig + ((rg >> 1) << 2);
                    float x  = Xs[r * PJSTR + kcol];
                    uint32_t hb = __float_as_uint(x) & 0xFFFFE000u;
                    ahi[f][rg] = hb;
                    alo[f][rg] = __float_as_uint(x - __uint_as_float(hb));
                }
            }
#pragma unroll
            for (int j = 0; j < 8; j++) {
                int cidx = warp_n * 64 + j * 8 + gid;
                float b0f = Ws[cidx * PJSTR + kk + tig];
                float b1f = Ws[cidx * PJSTR + kk + tig + 4];
                uint32_t b0h = __float_as_uint(b0f) & 0xFFFFE000u;
                uint32_t b1h = __float_as_uint(b1f) & 0xFFFFE000u;
                uint32_t b0l = __float_as_uint(b0f - __uint_as_float(b0h));
                uint32_t b1l = __float_as_uint(b1f - __uint_as_float(b1h));
#pragma unroll
                for (int f = 0; f < 2; f++) {
                    MMA_TF32(c[f][j], ahi[f][0], ahi[f][1], ahi[f][2], ahi[f][3], b0h, b1h);
                    MMA_TF32(c[f][j], ahi[f][0], ahi[f][1], ahi[f][2], ahi[f][3], b0l, b1l);
                    MMA_TF32(c[f][j], alo[f][0], alo[f][1], alo[f][2], alo[f][3], b0h, b1h);
                }
            }
        }
        __syncthreads();
    }

#pragma unroll
    for (int f = 0; f < 2; f++) {
        int rloc = warp_m * 32 + f * 16 + gid;
#pragma unroll
        for (int j = 0; j < 8; j++) {
            int cc = col0 + warp_n * 64 + j * 8 + 2 * tig;
#pragma unroll
            for (int h = 0; h < 2; h++) {
                int r = row0 + rloc + h * 8;
                *(float2*)(Yout + (size_t)r * 512 + cc) =
                    make_float2(c[f][j][h * 2], c[f][j][h * 2 + 1]);
            }
        }
    }
}

// ---------------------------------------------------------------------------
// PE transpose prep: gpe[j][d] = tf32(pe[d][j])
// ---------------------------------------------------------------------------
__global__ void pe_prep_kernel(const float* __restrict__ pe) {
    int idx = blockIdx.x * 256 + threadIdx.x;
    if (idx < Ll * Dd) {
        int j = idx >> 6, d = idx & 63;
        gpe[idx] = to_tf32(pe[d * Ll + j]);
    }
}

// ---------------------------------------------------------------------------
// Single-pass tf32 MMA banded attention (unchanged from round 4).
// ---------------------------------------------------------------------------
#define QSTR 68
#define KSTR 68
#define VSTR 132
#define PSTR2 132
#define OFF_Q    0
#define OFF_K    (OFF_Q + 64 * QSTR)
#define OFF_V    (OFF_K + 128 * KSTR)
#define OFF_PE   (OFF_V + 64 * VSTR)
#define OFF_SREL (OFF_PE + 64 * QSTR)
#define OFF_SPE  (OFF_SREL + 64 * QSTR)
#define OFF_CORR (OFF_SPE + 64 * QSTR)
#define OFF_LINV (OFF_CORR + 64)
#define ATTN_SMEM_FLOATS (OFF_LINV + 64)
#define OFF_P    OFF_K

__global__ __launch_bounds__(256) void attn_mma_kernel(
        const float* __restrict__ span_val) {
    extern __shared__ float sm[];
    float* Qs   = sm + OFF_Q;
    float* Ks   = sm + OFF_K;
    float* Vs   = sm + OFF_V;
    float* PEs  = sm + OFF_PE;
    float* Srel = sm + OFF_SREL;
    float* Spe  = sm + OFF_SPE;
    float* corr_s = sm + OFF_CORR;
    float* linv_s = sm + OFF_LINV;
    float* Ps   = sm + OFF_P;

    const uint32_t* Qu  = (const uint32_t*)Qs;
    const uint32_t* Ku  = (const uint32_t*)Ks;
    const uint32_t* Vu  = (const uint32_t*)Vs;
    const uint32_t* PEu = (const uint32_t*)PEs;
    const uint32_t* Pu  = (const uint32_t*)Ps;

    const int tid  = threadIdx.x;
    const int lane = tid & 31;
    const int wid  = tid >> 5;
    const int gid  = lane >> 2;
    const int tig  = lane & 3;
    const int bk   = blockIdx.y;
    const int i0   = blockIdx.x * 64;
    const int kh   = bk & 7;

    const int m0  = (wid & 3) * 16;
    const int nq0 = (wid >> 2) * 64;
    const int np0 = (wid >> 2) * 32;

    const int srow = tid >> 2;
    const int tg4  = tid & 3;
    const int tbase = tg4 * 16;
    const float spanL = span_val[kh] * 1024.f;

    {
        const float* gqp = gq + ((size_t)bk * Mm + i0) * Dd;
#pragma unroll
        for (int it = 0; it < 4; it++) {
            int idx = tid + it * 256;
            int r = idx >> 4, c4 = (idx & 15) << 2;
            *(float4*)&Qs[r * QSTR + c4] = *(const float4*)(gqp + (size_t)r * Dd + c4);
        }
    }

    float oacc[4][4];
#pragma unroll
    for (int j = 0; j < 4; j++)
#pragma unroll
        for (int t = 0; t < 4; t++) oacc[j][t] = 0.f;

    float m_run = -1e30f, l_run = 0.f;

    for (int jc = 0; jc < Ll; jc += 64) {
        __syncthreads();
        {
            const float* gkp = gk + ((size_t)bk * SKk + i0 + jc) * Dd;
#pragma unroll
            for (int it = 0; it < 8; it++) {
                int idx = tid + it * 256;
                int r = idx >> 4, c4 = (idx & 15) << 2;
                *(float4*)&Ks[r * KSTR + c4] = *(const float4*)(gkp + (size_t)r * Dd + c4);
            }
            const float* gvp = gv + (size_t)bk * Dd * SKk + i0 + jc;
#pragma unroll
            for (int it = 0; it < 8; it++) {
                int idx = tid + it * 256;
                int d = idx >> 5, c4 = (idx & 31) << 2;
                *(float4*)&Vs[d * VSTR + c4] = *(const float4*)(gvp + (size_t)d * SKk + c4);
            }
            const float* gpp = gpe + (size_t)jc * Dd;
#pragma unroll
            for (int it = 0; it < 4; it++) {
                int idx = tid + it * 256;
                int r = idx >> 4, c4 = (idx & 15) << 2;
                *(float4*)&PEs[r * QSTR + c4] = *(const float4*)(gpp + (size_t)r * Dd + c4);
            }
        }
        __syncthreads();

        float sacc[8][4], pacc[4][4];
#pragma unroll
        for (int j = 0; j < 8; j++)
#pragma unroll
            for (int t = 0; t < 4; t++) sacc[j][t] = 0.f;
#pragma unroll
        for (int j = 0; j < 4; j++)
#pragma unroll
            for (int t = 0; t < 4; t++) pacc[j][t] = 0.f;

#pragma unroll
        for (int k0 = 0; k0 < 64; k0 += 8) {
            int ar = (m0 + gid) * QSTR + k0 + tig;
            uint32_t a0 = Qu[ar];
            uint32_t a1 = Qu[ar + 8 * QSTR];
            uint32_t a2 = Qu[ar + 4];
            uint32_t a3 = Qu[ar + 8 * QSTR + 4];
#pragma unroll
            for (int j = 0; j < 8; j++) {
                int br = (nq0 + 8 * j + gid) * KSTR + k0 + tig;
                MMA_TF32(sacc[j], a0, a1, a2, a3, Ku[br], Ku[br + 4]);
            }
#pragma unroll
            for (int j = 0; j < 4; j++) {
                int br = (np0 + 8 * j + gid) * QSTR + k0 + tig;
                MMA_TF32(pacc[j], a0, a1, a2, a3, PEu[br], PEu[br + 4]);
            }
        }

#pragma unroll
        for (int j = 0; j < 8; j++) {
            int col = nq0 + 8 * j + 2 * tig;
            int r0 = m0 + gid, r1 = r0 + 8;
            int t00 = col - r0, t10 = col - r1;
            if ((unsigned)t00 < 64u)       Srel[r0 * QSTR + t00]     = sacc[j][0];
            if ((unsigned)(t00 + 1) < 64u) Srel[r0 * QSTR + t00 + 1] = sacc[j][1];
            if ((unsigned)t10 < 64u)       Srel[r1 * QSTR + t10]     = sacc[j][2];
            if ((unsigned)(t10 + 1) < 64u) Srel[r1 * QSTR + t10 + 1] = sacc[j][3];
        }
#pragma unroll
        for (int j = 0; j < 4; j++) {
            int col = np0 + 8 * j + 2 * tig;
            Spe[(m0 + gid) * QSTR + col]     = pacc[j][0];
            Spe[(m0 + gid) * QSTR + col + 1] = pacc[j][1];
            Spe[(m0 + gid + 8) * QSTR + col]     = pacc[j][2];
            Spe[(m0 + gid + 8) * QSTR + col + 1] = pacc[j][3];
        }
        __syncthreads();

        {
            float s[16];
            float mloc = -1e30f;
#pragma unroll
            for (int e = 0; e < 16; e++) {
                s[e] = (Srel[srow * QSTR + tbase + e] + Spe[srow * QSTR + tbase + e]) * SCALE;
                mloc = fmaxf(mloc, s[e]);
            }
            mloc = fmaxf(mloc, __shfl_xor_sync(0xFFFFFFFFu, mloc, 1));
            mloc = fmaxf(mloc, __shfl_xor_sync(0xFFFFFFFFu, mloc, 2));
            float m_new = fmaxf(m_run, mloc);
            float corr  = __expf(m_run - m_new);
            l_run *= corr;
            float p[16], psum = 0.f;
#pragma unroll
            for (int e = 0; e < 16; e++) { p[e] = __expf(s[e] - m_new); psum += p[e]; }
            psum += __shfl_xor_sync(0xFFFFFFFFu, psum, 1);
            psum += __shfl_xor_sync(0xFFFFFFFFu, psum, 2);
            l_run += psum;
            m_run = m_new;
            if (tg4 == 0) corr_s[srow] = corr;

#pragma unroll
            for (int e = 0; e < 16; e++) {
                int t = tbase + e;
                float jj = (float)(jc + t);
                float mk = fminf(1.f, fmaxf(0.f, (jj - 1023.f + spanL) * (1.f / 32.f) + 1.f));
                float pm = to_tf32(p[e] * mk);
                int u = srow + t;
                Ps[srow * PSTR2 + u] = pm;
                int uz = (t < srow) ? t : t + 64;
                Ps[srow * PSTR2 + uz] = 0.f;
            }
        }
        __syncthreads();

        {
            float cA = corr_s[m0 + gid], cB = corr_s[m0 + gid + 8];
#pragma unroll
            for (int j = 0; j < 4; j++) {
                oacc[j][0] *= cA; oacc[j][1] *= cA;
                oacc[j][2] *= cB; oacc[j][3] *= cB;
            }
#pragma unroll
            for (int k0 = 0; k0 < 128; k0 += 8) {
                int ar = (m0 + gid) * PSTR2 + k0 + tig;
                uint32_t a0 = Pu[ar];
                uint32_t a1 = Pu[ar + 8 * PSTR2];
                uint32_t a2 = Pu[ar + 4];
                uint32_t a3 = Pu[ar + 8 * PSTR2 + 4];
#pragma unroll
                for (int j = 0; j < 4; j++) {
                    int br = (np0 + 8 * j + gid) * VSTR + k0 + tig;
                    MMA_TF32(oacc[j], a0, a1, a2, a3, Vu[br], Vu[br + 4]);
                }
            }
        }
    }

    __syncthreads();
    if (tg4 == 0) linv_s[srow] = 1.f / l_run;
    __syncthreads();

    {
        float lA = linv_s[m0 + gid], lB = linv_s[m0 + gid + 8];
        int b = bk >> 3;
        int r0 = i0 + m0 + gid;
#pragma unroll
        for (int j = 0; j < 4; j++) {
            int col = np0 + 8 * j + 2 * tig;
            float* p0 = g_ctx + ((size_t)(b * Mm + r0) * Kk + kh) * Dd + col;
            float* p1 = g_ctx + ((size_t)(b * Mm + r0 + 8) * Kk + kh) * Dd + col;
            *(float2*)p0 = make_float2(oacc[j][0] * lA, oacc[j][1] * lA);
            *(float2*)p1 = make_float2(oacc[j][2] * lB, oacc[j][3] * lB);
        }
    }
}

// ---------------------------------------------------------------------------
extern "C" void kernel_launch(void* const* d_in, const int* in_sizes, int n_in,
                              void* d_out, int out_size) {
    const float* query = (const float*)d_in[0];
    const float* key   = (const float*)d_in[1];
    const float* value = (const float*)d_in[2];
    const float* pe    = (const float*)d_in[3];
    const float* Wq    = (const float*)d_in[4];
    const float* Wk    = (const float*)d_in[5];
    const float* Wv    = (const float*)d_in[6];
    const float* Wo    = (const float*)d_in[7];
    const float* span  = (const float*)d_in[8];
    float* out = (float*)d_out;

    cudaFuncSetAttribute(attn_mma_kernel,
                         cudaFuncAttributeMaxDynamicSharedMemorySize,
                         ATTN_SMEM_FLOATS * (int)sizeof(float));

    proj_qkv_kernel<<<dim3(Bb * Mm / 128, 4), 256>>>(query, Wq, Mm, 0);
    proj_qkv_kernel<<<dim3(Bb * SKk / 128, 4), 256>>>(key, Wk, SKk, 1);
    proj_qkv_kernel<<<dim3(Bb * SKk / 128, 4), 256>>>(value, Wv, SKk, 2);
    pe_prep_kernel<<<(Ll * Dd + 255) / 256, 256>>>(pe);

    attn_mma_kernel<<<dim3(Mm / 64, BKC), 256,
                      ATTN_SMEM_FLOATS * (int)sizeof(float)>>>(span);

    proj_out_kernel<<<dim3(Bb * Mm / 128, 4), 256>>>(Wo, out);
}